// round 6
// baseline (speedup 1.0000x reference)
#include <cuda_runtime.h>
#include <cstdint>

#define N_NODES 50000
#define N_EDGES 800000
#define IN_DIM  256
#define HIDDEN  128
#define OUT_DIM 64
#define NEG_SLOPE 0.1f

// Scratch (device globals: allocation-free rule)
__device__ __align__(16) float g_h0[N_NODES * HIDDEN];  // activations
__device__ __align__(16) float g_h1[N_NODES * HIDDEN];  // transformed feats (prescaled by dinv)
__device__ float g_dinv[N_NODES];
__device__ int   g_cnt[N_NODES];
__device__ int   g_fill[N_NODES];
__device__ int   g_rowptr[N_NODES + 1];
__device__ int   g_srcidx[N_EDGES];
__device__ int   g_is64;

#define BUF_EXT 0
#define BUF_H0  1

// ---------------------------------------------------------------------------
// f32x2 packed FMA (sm_103a FFMA2 — only reachable via PTX)
// ---------------------------------------------------------------------------
__device__ __forceinline__ unsigned long long ffma2(
    unsigned long long a, unsigned long long b, unsigned long long c)
{
    unsigned long long d;
    asm("fma.rn.f32x2 %0, %1, %2, %3;" : "=l"(d) : "l"(a), "l"(b), "l"(c));
    return d;
}
__device__ __forceinline__ float2 u2f(unsigned long long v) {
    float2 f;
    asm("mov.b64 {%0,%1}, %2;" : "=f"(f.x), "=f"(f.y) : "l"(v));
    return f;
}

// ---------------------------------------------------------------------------
// Init + dtype detection
// ---------------------------------------------------------------------------
__global__ void k_init() {
    int i = blockIdx.x * blockDim.x + threadIdx.x;
    if (i < N_NODES) { g_cnt[i] = 0; g_fill[i] = 0; }
    if (i == 0) g_is64 = 1;
}

// int64 edge_index with values < 50000 => every odd 32-bit word is zero.
__global__ void k_detect(const unsigned* __restrict__ e) {
    int i = blockIdx.x * blockDim.x + threadIdx.x;
    if (i < 4096) {
        if (e[2 * i + 1] != 0u) g_is64 = 0;
    }
}

__device__ __forceinline__ int edge_src(const void* ei, int e) {
    return g_is64 ? (int)((const long long*)ei)[e] : ((const int*)ei)[e];
}
__device__ __forceinline__ int edge_dst(const void* ei, int e) {
    return g_is64 ? (int)((const long long*)ei)[N_EDGES + e]
                  : ((const int*)ei)[N_EDGES + e];
}

// ---------------------------------------------------------------------------
// CSR build: histogram -> dinv -> scan -> placement
// ---------------------------------------------------------------------------
__global__ void k_hist(const void* __restrict__ ei) {
    int e = blockIdx.x * blockDim.x + threadIdx.x;
    if (e < N_EDGES) atomicAdd(&g_cnt[edge_dst(ei, e)], 1);
}

__global__ void k_dinv() {
    int i = blockIdx.x * blockDim.x + threadIdx.x;
    if (i < N_NODES) g_dinv[i] = rsqrtf((float)g_cnt[i] + 1.0f);  // +1 self loop
}

__global__ __launch_bounds__(1024) void k_scan() {
    __shared__ int ssum[1024];
    const int t = threadIdx.x;
    const int CH = 49;
    int base = t * CH;
    int s = 0;
    for (int j = 0; j < CH; j++) {
        int idx = base + j;
        if (idx < N_NODES) s += g_cnt[idx];
    }
    ssum[t] = s;
    __syncthreads();
    for (int off = 1; off < 1024; off <<= 1) {
        int v = (t >= off) ? ssum[t - off] : 0;
        __syncthreads();
        ssum[t] += v;
        __syncthreads();
    }
    int ex = (t == 0) ? 0 : ssum[t - 1];
    for (int j = 0; j < CH; j++) {
        int idx = base + j;
        if (idx < N_NODES) { g_rowptr[idx] = ex; ex += g_cnt[idx]; }
    }
    if (t == 1023) g_rowptr[N_NODES] = ssum[1023];
}

__global__ void k_place(const void* __restrict__ ei) {
    int e = blockIdx.x * blockDim.x + threadIdx.x;
    if (e < N_EDGES) {
        int s = edge_src(ei, e);
        int d = edge_dst(ei, e);
        int pos = g_rowptr[d] + atomicAdd(&g_fill[d], 1);
        g_srcidx[pos] = s;
    }
}

// ---------------------------------------------------------------------------
// Tiled fp32 GEMM with packed FFMA2:  out[M,C] = A[M,K] @ W[K,C]
// MODE 0: +bias, leaky              (encoder: A=x ext,  out=g_h0)
// MODE 1: +bias                     (decoder: A=g_h0,   out=ext)
// MODE 3: *dinv[m] prescale         (conv:    A=g_h0,   out=g_h1)
// A-tile stored DUPLICATED in smem: xs2[row][k] = {a, a} so the inner loop
// needs no pack ALU — LDS.64 broadcast feeds FFMA2 directly.
// ---------------------------------------------------------------------------
template <int K, int C, int MODE, int SRC>
__global__ __launch_bounds__(256)
void k_gemm(const float* __restrict__ Aext, const float* __restrict__ W,
            const float* __restrict__ bias, float* __restrict__ Oext)
{
    const float* A   = (SRC == BUF_H0) ? g_h0 : Aext;
    float*       out = (MODE == 0) ? g_h0 : ((MODE == 3) ? g_h1 : Oext);

    constexpr int TM = 32, TK = 64;
    constexpr int CG = C / 4;          // col groups of 4 (2 f32x2 pairs)
    constexpr int RG = 256 / CG;
    constexpr int RPT = TM / RG;

    __shared__ float2 xs2[TM][TK];     // duplicated A tile: 16 KB
    __shared__ float  ws[TK][C];       // W tile: up to 32 KB

    const int m0  = blockIdx.x * TM;
    const int tid = threadIdx.x;
    const int cg  = tid % CG;
    const int rg  = tid / CG;

    unsigned long long acc[RPT][2];
#pragma unroll
    for (int r = 0; r < RPT; r++) { acc[r][0] = 0ull; acc[r][1] = 0ull; }

    for (int kt = 0; kt < K; kt += TK) {
        // stage A tile duplicated (zero-pad past M)
#pragma unroll
        for (int i = tid; i < TM * TK / 4; i += 256) {
            int row = (i * 4) / TK, col = (i * 4) % TK;
            int m = m0 + row;
            float4 v = make_float4(0.f, 0.f, 0.f, 0.f);
            if (m < N_NODES)
                v = *(const float4*)&A[(size_t)m * K + kt + col];
            xs2[row][col + 0] = make_float2(v.x, v.x);
            xs2[row][col + 1] = make_float2(v.y, v.y);
            xs2[row][col + 2] = make_float2(v.z, v.z);
            xs2[row][col + 3] = make_float2(v.w, v.w);
        }
        // stage W tile
#pragma unroll
        for (int i = tid; i < TK * C / 4; i += 256) {
            int row = (i * 4) / C, col = (i * 4) % C;
            *(float4*)&ws[row][col] = *(const float4*)&W[(size_t)(kt + row) * C + col];
        }
        __syncthreads();

#pragma unroll
        for (int k = 0; k < TK; k++) {
            ulonglong2 wv = *(const ulonglong2*)&ws[k][cg * 4];  // 2 packed col-pairs
#pragma unroll
            for (int r = 0; r < RPT; r++) {
                unsigned long long aa =
                    *(const unsigned long long*)&xs2[rg * RPT + r][k]; // {a,a}
                acc[r][0] = ffma2(aa, wv.x, acc[r][0]);
                acc[r][1] = ffma2(aa, wv.y, acc[r][1]);
            }
        }
        __syncthreads();
    }

#pragma unroll
    for (int r = 0; r < RPT; r++) {
        int m = m0 + rg * RPT + r;
        if (m >= N_NODES) continue;
        int c = cg * 4;
        float2 p0 = u2f(acc[r][0]);
        float2 p1 = u2f(acc[r][1]);
        float4 v = make_float4(p0.x, p0.y, p1.x, p1.y);
        if (MODE == 0 || MODE == 1) {
            v.x += bias[c]; v.y += bias[c + 1]; v.z += bias[c + 2]; v.w += bias[c + 3];
        }
        if (MODE == 0) {
            v.x = v.x > 0.f ? v.x : NEG_SLOPE * v.x;
            v.y = v.y > 0.f ? v.y : NEG_SLOPE * v.y;
            v.z = v.z > 0.f ? v.z : NEG_SLOPE * v.z;
            v.w = v.w > 0.f ? v.w : NEG_SLOPE * v.w;
        }
        if (MODE == 3) {
            float di = g_dinv[m];
            v.x *= di; v.y *= di; v.z *= di; v.w *= di;
        }
        *(float4*)&out[(size_t)m * C + c] = v;
    }
}

// ---------------------------------------------------------------------------
// Aggregation (gather): one warp per dst node, lane handles 4 of 128 dims.
// h1 is prescaled by dinv, so:
//   h0[d] = leaky( dinv[d] * ( h1'[d] + sum_{s in CSR(d)} h1'[s] ) + bias )
// src indices fetched 32-at-a-time per warp and broadcast via shfl (MLP).
// ---------------------------------------------------------------------------
__global__ __launch_bounds__(256)
void k_gather(const float* __restrict__ bias)
{
    int d    = (blockIdx.x * blockDim.x + threadIdx.x) >> 5;
    int lane = threadIdx.x & 31;
    if (d >= N_NODES) return;

    float dd  = g_dinv[d];
    int   beg = g_rowptr[d], end = g_rowptr[d + 1];

    float4 acc = *(const float4*)&g_h1[(size_t)d * HIDDEN + lane * 4]; // self

    for (int j0 = beg; j0 < end; j0 += 32) {
        int n = min(32, end - j0);
        int myidx = (j0 + lane < end) ? g_srcidx[j0 + lane] : 0;
        for (int c = 0; c < n; c++) {
            int s = __shfl_sync(0xffffffffu, myidx, c);
            float4 u = *(const float4*)&g_h1[(size_t)s * HIDDEN + lane * 4];
            acc.x += u.x; acc.y += u.y; acc.z += u.z; acc.w += u.w;
        }
    }

    int c = lane * 4;
    acc.x = acc.x * dd + bias[c];
    acc.y = acc.y * dd + bias[c + 1];
    acc.z = acc.z * dd + bias[c + 2];
    acc.w = acc.w * dd + bias[c + 3];
    acc.x = acc.x > 0.f ? acc.x : NEG_SLOPE * acc.x;
    acc.y = acc.y > 0.f ? acc.y : NEG_SLOPE * acc.y;
    acc.z = acc.z > 0.f ? acc.z : NEG_SLOPE * acc.z;
    acc.w = acc.w > 0.f ? acc.w : NEG_SLOPE * acc.w;
    *(float4*)&g_h0[(size_t)d * HIDDEN + c] = acc;
}

// ---------------------------------------------------------------------------
// Launch
// ---------------------------------------------------------------------------
extern "C" void kernel_launch(void* const* d_in, const int* in_sizes, int n_in,
                              void* d_out, int out_size)
{
    const float* x      = (const float*)d_in[0];
    const void*  ei     = d_in[1];                 // int32 or int64, detected
    const float* enc_W  = (const float*)d_in[2];
    const float* enc_b  = (const float*)d_in[3];
    const float* conv_W = (const float*)d_in[4];   // [2,128,128]
    const float* conv_b = (const float*)d_in[5];   // [2,128]
    const float* dec_W  = (const float*)d_in[6];
    const float* dec_b  = (const float*)d_in[7];
    float*       out    = (float*)d_out;

    const int nodeBlocks = (N_NODES + 255) / 256;
    const int edgeBlocks = (N_EDGES + 255) / 256;
    const int gemmBlocks = (N_NODES + 31) / 32;
    const int gathBlocks = (N_NODES * 32 + 255) / 256;

    k_init<<<nodeBlocks, 256>>>();
    k_detect<<<16, 256>>>((const unsigned*)ei);
    k_hist<<<edgeBlocks, 256>>>(ei);
    k_dinv<<<nodeBlocks, 256>>>();
    k_scan<<<1, 1024>>>();
    k_place<<<edgeBlocks, 256>>>(ei);

    // encoder: h0 = leaky(x @ enc_W + enc_b)
    k_gemm<IN_DIM, HIDDEN, 0, BUF_EXT><<<gemmBlocks, 256>>>(x, enc_W, enc_b, nullptr);

    for (int l = 0; l < 2; l++) {
        const float* W = conv_W + (size_t)l * HIDDEN * HIDDEN;
        const float* b = conv_b + (size_t)l * HIDDEN;
        // g_h1 = (h0 @ W) * dinv  (prescaled transform)
        k_gemm<HIDDEN, HIDDEN, 3, BUF_H0><<<gemmBlocks, 256>>>(nullptr, W, nullptr, nullptr);
        // h0 = leaky(dinv * (h1'[self] + sum h1'[src]) + b)
        k_gather<<<gathBlocks, 256>>>(b);
    }

    // decoder: out = h0 @ dec_W + dec_b
    k_gemm<HIDDEN, OUT_DIM, 1, BUF_H0><<<gemmBlocks, 256>>>(nullptr, dec_W, dec_b, out);
}

// round 8
// speedup vs baseline: 1.0741x; 1.0741x over previous
#include <cuda_runtime.h>
#include <cstdint>

#define N_NODES 50000
#define N_EDGES 800000
#define IN_DIM  256
#define HIDDEN  128
#define OUT_DIM 64
#define NEG_SLOPE 0.1f

// Scratch (device globals: allocation-free rule)
__device__ __align__(16) float g_h0[N_NODES * HIDDEN];  // activations
__device__ __align__(16) float g_h1[N_NODES * HIDDEN];  // transformed feats (prescaled)
__device__ float g_dinv[N_NODES];
__device__ int   g_cnt[N_NODES];
__device__ int   g_fill[N_NODES];
__device__ int   g_rowptr[N_NODES + 1];
__device__ int   g_srcidx[N_EDGES];
__device__ int   g_is64;

#define BUF_EXT 0
#define BUF_H0  1

// ---------------------------------------------------------------------------
// tf32 helpers (3xTF32 split: D = Ah*Bh + Ah*Bl + Al*Bh, fp32 accumulate)
// ---------------------------------------------------------------------------
__device__ __forceinline__ uint32_t f2tf32(float x) {
    uint32_t u;
    asm("cvt.rna.tf32.f32 %0, %1;" : "=r"(u) : "f"(x));
    return u;
}

#define MMA_TF32(D, a, b) \
    asm volatile("mma.sync.aligned.m16n8k8.row.col.f32.tf32.tf32.f32 " \
        "{%0,%1,%2,%3}, {%4,%5,%6,%7}, {%8,%9}, {%0,%1,%2,%3};" \
        : "+f"((D)[0]), "+f"((D)[1]), "+f"((D)[2]), "+f"((D)[3]) \
        : "r"((a).x), "r"((a).y), "r"((a).z), "r"((a).w), "r"((b).x), "r"((b).y))

// ---------------------------------------------------------------------------
// Init + dtype detection
// ---------------------------------------------------------------------------
__global__ void k_init() {
    int i = blockIdx.x * blockDim.x + threadIdx.x;
    if (i < N_NODES) { g_cnt[i] = 0; g_fill[i] = 0; }
    if (i == 0) g_is64 = 1;
}
// int64 edge_index with values < 50000 => every odd 32-bit word is zero.
__global__ void k_detect(const unsigned* __restrict__ e) {
    int i = blockIdx.x * blockDim.x + threadIdx.x;
    if (i < 4096) { if (e[2 * i + 1] != 0u) g_is64 = 0; }
}
__device__ __forceinline__ int edge_src(const void* ei, int e) {
    return g_is64 ? (int)((const long long*)ei)[e] : ((const int*)ei)[e];
}
__device__ __forceinline__ int edge_dst(const void* ei, int e) {
    return g_is64 ? (int)((const long long*)ei)[N_EDGES + e] : ((const int*)ei)[N_EDGES + e];
}

// ---------------------------------------------------------------------------
// CSR build
// ---------------------------------------------------------------------------
__global__ void k_hist(const void* __restrict__ ei) {
    int e = blockIdx.x * blockDim.x + threadIdx.x;
    if (e < N_EDGES) atomicAdd(&g_cnt[edge_dst(ei, e)], 1);
}
__global__ void k_dinv() {
    int i = blockIdx.x * blockDim.x + threadIdx.x;
    if (i < N_NODES) g_dinv[i] = rsqrtf((float)g_cnt[i] + 1.0f);
}
__global__ __launch_bounds__(1024) void k_scan() {
    __shared__ int ssum[1024];
    const int t = threadIdx.x, CH = 49;
    int base = t * CH, s = 0;
    for (int j = 0; j < CH; j++) { int idx = base + j; if (idx < N_NODES) s += g_cnt[idx]; }
    ssum[t] = s; __syncthreads();
    for (int off = 1; off < 1024; off <<= 1) {
        int v = (t >= off) ? ssum[t - off] : 0;
        __syncthreads(); ssum[t] += v; __syncthreads();
    }
    int ex = (t == 0) ? 0 : ssum[t - 1];
    for (int j = 0; j < CH; j++) {
        int idx = base + j;
        if (idx < N_NODES) { g_rowptr[idx] = ex; ex += g_cnt[idx]; }
    }
    if (t == 1023) g_rowptr[N_NODES] = ssum[1023];
}
__global__ void k_place(const void* __restrict__ ei) {
    int e = blockIdx.x * blockDim.x + threadIdx.x;
    if (e < N_EDGES) {
        int s = edge_src(ei, e), d = edge_dst(ei, e);
        g_srcidx[g_rowptr[d] + atomicAdd(&g_fill[d], 1)] = s;
    }
}

// ---------------------------------------------------------------------------
// 3xTF32 mma.sync GEMM: out[M=128/blk, N] = A[*, K] @ W[K, N]
// Block 256 thr = 8 warps in 4(M) x 2(N) grid; warp tile 32 x N/2.
// Fragments staged in fragment-order smem (LDS.128 / LDS.64, conflict-free).
// MODE 0: +bias+leaky -> g_h0 (encoder)   MODE 1: +bias -> ext (decoder)
// MODE 3: *dinv[m]    -> g_h1 (conv transform, prescaled)
// ---------------------------------------------------------------------------
template <int K, int N, int MODE, int SRC>
__global__ __launch_bounds__(256)
void k_mma_gemm(const float* __restrict__ Aext, const float* __restrict__ W,
                const float* __restrict__ bias, float* __restrict__ Oext)
{
    constexpr int KC  = 16;          // K columns per staged chunk
    constexpr int KT  = KC / 8;      // k-tiles per chunk = 2
    constexpr int NTW = N / 16;      // n-tiles per warp (8 for N=128, 4 for N=64)

    __shared__ uint32_t sAh[128 * KC], sAl[128 * KC];   // 8KB each
    __shared__ uint32_t sBh[KC * N],   sBl[KC * N];     // 8KB each (N=128)

    const float* A   = (SRC == BUF_H0) ? g_h0 : Aext;
    float*       out = (MODE == 0) ? g_h0 : ((MODE == 3) ? g_h1 : Oext);

    const int tid    = threadIdx.x;
    const int wid    = tid >> 5;
    const int lane   = tid & 31;
    const int warp_m = wid >> 1;          // 0..3
    const int warp_n = wid & 1;           // 0..1
    const int gq     = lane >> 2;         // group id 0..7
    const int tq     = lane & 3;          // thread-in-group 0..3
    const int m0     = blockIdx.x * 128;

    float acc[2][NTW][4];
#pragma unroll
    for (int mt = 0; mt < 2; mt++)
#pragma unroll
        for (int nt = 0; nt < NTW; nt++)
#pragma unroll
            for (int j = 0; j < 4; j++) acc[mt][nt][j] = 0.0f;

    for (int kt0 = 0; kt0 < K; kt0 += KC) {
        // ---- stage A fragments (hi/lo tf32) ----
        for (int i = tid; i < 128 * KC; i += 256) {
            int r = i / KC, kl = i % KC;
            int m = m0 + r;
            float v = (m < N_NODES) ? A[(size_t)m * K + kt0 + kl] : 0.0f;
            uint32_t hi = f2tf32(v);
            uint32_t lo = f2tf32(v - __uint_as_float(hi));
            int rb = r >> 4, rr = r & 15, kt = kl >> 3, t8 = kl & 7;
            int reg  = ((rr >> 3) & 1) | ((t8 >> 2) << 1);
            int ln   = ((rr & 7) << 2) | (t8 & 3);
            int off  = ((rb * KT + kt) * 32 + ln) * 4 + reg;
            sAh[off] = hi; sAl[off] = lo;
        }
        // ---- stage B fragments: B[k][n] = W[kt0+k][n] ----
        for (int i = tid; i < KC * N; i += 256) {
            int kl = i / N, n = i % N;
            float v = W[(size_t)(kt0 + kl) * N + n];
            uint32_t hi = f2tf32(v);
            uint32_t lo = f2tf32(v - __uint_as_float(hi));
            int nt = n >> 3, g = n & 7, kt = kl >> 3, t8 = kl & 7;
            int reg = (t8 >> 2) & 1;
            int ln  = (g << 2) | (t8 & 3);
            int off = ((nt * KT + kt) * 32 + ln) * 2 + reg;
            sBh[off] = hi; sBl[off] = lo;
        }
        __syncthreads();

#pragma unroll
        for (int kt = 0; kt < KT; kt++) {
            uint4 ah[2], al[2];
#pragma unroll
            for (int mt = 0; mt < 2; mt++) {
                int rb = warp_m * 2 + mt;
                ah[mt] = *(const uint4*)&sAh[((rb * KT + kt) * 32 + lane) * 4];
                al[mt] = *(const uint4*)&sAl[((rb * KT + kt) * 32 + lane) * 4];
            }
#pragma unroll
            for (int ntl = 0; ntl < NTW; ntl++) {
                int nt = warp_n * NTW + ntl;
                uint2 bh = *(const uint2*)&sBh[((nt * KT + kt) * 32 + lane) * 2];
                uint2 bl = *(const uint2*)&sBl[((nt * KT + kt) * 32 + lane) * 2];
#pragma unroll
                for (int mt = 0; mt < 2; mt++) {
                    MMA_TF32(acc[mt][ntl], ah[mt], bh);
                    MMA_TF32(acc[mt][ntl], ah[mt], bl);
                    MMA_TF32(acc[mt][ntl], al[mt], bh);
                }
            }
        }
        __syncthreads();
    }

    // ---- epilogue: D layout c0/c1 -> row g, cols 2t,2t+1; c2/c3 -> row g+8 ----
#pragma unroll
    for (int mt = 0; mt < 2; mt++) {
        int r0 = m0 + warp_m * 32 + mt * 16 + gq;
        int r1 = r0 + 8;
        float s0 = 1.0f, s1 = 1.0f;
        if (MODE == 3) {
            if (r0 < N_NODES) s0 = g_dinv[r0];
            if (r1 < N_NODES) s1 = g_dinv[r1];
        }
#pragma unroll
        for (int ntl = 0; ntl < NTW; ntl++) {
            int c0 = (warp_n * NTW + ntl) * 8 + 2 * tq;
            float b0 = 0.f, b1 = 0.f;
            if (MODE == 0 || MODE == 1) { b0 = bias[c0]; b1 = bias[c0 + 1]; }
            float d0 = acc[mt][ntl][0] + b0, d1 = acc[mt][ntl][1] + b1;
            float d2 = acc[mt][ntl][2] + b0, d3 = acc[mt][ntl][3] + b1;
            if (MODE == 0) {
                d0 = d0 > 0.f ? d0 : NEG_SLOPE * d0;
                d1 = d1 > 0.f ? d1 : NEG_SLOPE * d1;
                d2 = d2 > 0.f ? d2 : NEG_SLOPE * d2;
                d3 = d3 > 0.f ? d3 : NEG_SLOPE * d3;
            }
            if (MODE == 3) { d0 *= s0; d1 *= s0; d2 *= s1; d3 *= s1; }
            if (r0 < N_NODES) *(float2*)&out[(size_t)r0 * N + c0] = make_float2(d0, d1);
            if (r1 < N_NODES) *(float2*)&out[(size_t)r1 * N + c0] = make_float2(d2, d3);
        }
    }
}

// ---------------------------------------------------------------------------
// Aggregation gather: one warp per dst node; h1 prescaled by dinv.
// h0[d] = leaky(dinv[d]*(h1'[d] + sum h1'[src]) + bias)
// ---------------------------------------------------------------------------
__global__ __launch_bounds__(256)
void k_gather(const float* __restrict__ bias)
{
    int d    = (blockIdx.x * blockDim.x + threadIdx.x) >> 5;
    int lane = threadIdx.x & 31;
    if (d >= N_NODES) return;

    float dd  = g_dinv[d];
    int   beg = g_rowptr[d], end = g_rowptr[d + 1];

    float4 acc = *(const float4*)&g_h1[(size_t)d * HIDDEN + lane * 4];

    for (int j0 = beg; j0 < end; j0 += 32) {
        int n = min(32, end - j0);
        int myidx = (j0 + lane < end) ? g_srcidx[j0 + lane] : 0;
        for (int c = 0; c < n; c++) {
            int s = __shfl_sync(0xffffffffu, myidx, c);
            float4 u = *(const float4*)&g_h1[(size_t)s * HIDDEN + lane * 4];
            acc.x += u.x; acc.y += u.y; acc.z += u.z; acc.w += u.w;
        }
    }

    int c = lane * 4;
    acc.x = acc.x * dd + bias[c];     acc.y = acc.y * dd + bias[c + 1];
    acc.z = acc.z * dd + bias[c + 2]; acc.w = acc.w * dd + bias[c + 3];
    acc.x = acc.x > 0.f ? acc.x : NEG_SLOPE * acc.x;
    acc.y = acc.y > 0.f ? acc.y : NEG_SLOPE * acc.y;
    acc.z = acc.z > 0.f ? acc.z : NEG_SLOPE * acc.z;
    acc.w = acc.w > 0.f ? acc.w : NEG_SLOPE * acc.w;
    *(float4*)&g_h0[(size_t)d * HIDDEN + c] = acc;
}

// ---------------------------------------------------------------------------
// Launch
// ---------------------------------------------------------------------------
extern "C" void kernel_launch(void* const* d_in, const int* in_sizes, int n_in,
                              void* d_out, int out_size)
{
    const float* x      = (const float*)d_in[0];
    const void*  ei     = d_in[1];
    const float* enc_W  = (const float*)d_in[2];
    const float* enc_b  = (const float*)d_in[3];
    const float* conv_W = (const float*)d_in[4];
    const float* conv_b = (const float*)d_in[5];
    const float* dec_W  = (const float*)d_in[6];
    const float* dec_b  = (const float*)d_in[7];
    float*       out    = (float*)d_out;

    const int nodeBlocks = (N_NODES + 255) / 256;
    const int edgeBlocks = (N_EDGES + 255) / 256;
    const int mmaBlocks  = (N_NODES + 127) / 128;   // 391
    const int gathBlocks = (N_NODES * 32 + 255) / 256;

    k_init<<<nodeBlocks, 256>>>();
    k_detect<<<16, 256>>>((const unsigned*)ei);
    k_hist<<<edgeBlocks, 256>>>(ei);
    k_dinv<<<nodeBlocks, 256>>>();
    k_scan<<<1, 1024>>>();
    k_place<<<edgeBlocks, 256>>>(ei);

    // encoder: h0 = leaky(x @ enc_W + enc_b)
    k_mma_gemm<IN_DIM, HIDDEN, 0, BUF_EXT><<<mmaBlocks, 256>>>(x, enc_W, enc_b, nullptr);

    for (int l = 0; l < 2; l++) {
        const float* W = conv_W + (size_t)l * HIDDEN * HIDDEN;
        const float* b = conv_b + (size_t)l * HIDDEN;
        // g_h1 = (h0 @ W) * dinv
        k_mma_gemm<HIDDEN, HIDDEN, 3, BUF_H0><<<mmaBlocks, 256>>>(nullptr, W, nullptr, nullptr);
        // h0 = leaky(dinv * (h1'[self] + sum h1'[src]) + b)
        k_gather<<<gathBlocks, 256>>>(b);
    }

    // decoder: out = h0 @ dec_W + dec_b
    k_mma_gemm<HIDDEN, OUT_DIM, 1, BUF_H0><<<mmaBlocks, 256>>>(nullptr, dec_W, dec_b, out);
}